// round 5
// baseline (speedup 1.0000x reference)
#include <cuda_runtime.h>

// Problem constants
#define LDIM   128
#define RDIM   2048
#define EDIM   32
#define FDIM   64
#define KTOT   2048      // EDIM*FDIM, contiguous k per row
#define BATCH  8

// Tiling
#define KT      16       // k per stage
#define RT      128      // r per CTA
#define ECH     4        // e per CTA
#define NSTAGE  ((ECH*FDIM)/KT)   // 16
#define NTHREADS 256

// rbf(d,e) = exp(-((d-mu_e)/sigma)^2) = 2^( -(KC*(d-mu_e))^2 )
// sigma = -0.375 (squared), KC = sqrt(log2(e))/0.375
#define KC_CONST   3.2029930899845557f
#define MU_STEP    (12.0f/31.0f)

__device__ __forceinline__ unsigned long long dup2(float x) {
    unsigned long long r;
    unsigned int u = __float_as_uint(x);
    asm("mov.b64 %0, {%1, %1};" : "=l"(r) : "r"(u));
    return r;
}
__device__ __forceinline__ void fma2(unsigned long long &acc,
                                     unsigned long long a,
                                     unsigned long long b) {
    asm("fma.rn.f32x2 %0, %1, %2, %0;" : "+l"(acc) : "l"(a), "l"(b));
}
__device__ __forceinline__ void unpack2(unsigned long long v, float &lo, float &hi) {
    unsigned int a, b;
    asm("mov.b64 {%0, %1}, %2;" : "=r"(a), "=r"(b) : "l"(v));
    lo = __uint_as_float(a);
    hi = __uint_as_float(b);
}
__device__ __forceinline__ float ex2_approx(float x) {
    float r;
    asm("ex2.approx.ftz.f32 %0, %1;" : "=f"(r) : "f"(x));
    return r;
}
__device__ __forceinline__ float sqrt_approx(float x) {
    float r;
    asm("sqrt.approx.f32 %0, %1;" : "=f"(r) : "f"(x));
    return r;
}

__global__ void ff_init_kernel(float* out) {
    if (threadIdx.x < BATCH) out[threadIdx.x] = 0.0f;
}

__global__ void __launch_bounds__(NTHREADS, 1)
ff_main_kernel(const float* __restrict__ ligf,
               const float* __restrict__ recf,
               const float* __restrict__ ligc,
               const float* __restrict__ recc,
               float* __restrict__ out)
{
    // Shared: As duplicated pairs [2][KT][128] u64 = 32 KB, Bs [2][KT][128] f32 = 16 KB
    __shared__ unsigned long long smem_u64[49152 / 8];
    unsigned long long* As2 = smem_u64;                       // 2*KT*128 u64
    float* Bs = (float*)(smem_u64 + 2 * KT * 128);            // 2*KT*128 f32

    const int tid = threadIdx.x;
    const int tx = tid & 15;          // r-tile position (8 r's each)
    const int ty = tid >> 4;          // l-tile position (8 l's each)

    const int rt = blockIdx.x;        // 0..15
    const int ec = blockIdx.y;        // 0..7
    const int b  = blockIdx.z;        // 0..7

    const int r0    = rt * RT;
    const int e0    = ec * ECH;
    const int kbase = e0 * FDIM;

    const float* Ag = ligf + (size_t)b * LDIM * KTOT + kbase;
    const float* Bg = recf + (size_t)b * RDIM * KTOT + (size_t)r0 * KTOT + kbase;

    // tile-load assignment: each thread loads rows (lrow, lrow+64), 4 consecutive k
    const int lrow = tid >> 2;            // 0..63
    const int lcol = (tid & 3) * 4;       // 0,4,8,12

    // ---- distances for this thread's 8x8 pairs ----
    float dist[8][8];
    {
        float lx[8], ly[8], lz[8];
        #pragma unroll
        for (int i = 0; i < 8; i++) {
            const float* p = ligc + ((size_t)b * LDIM + ty * 8 + i) * 3;
            lx[i] = p[0]; ly[i] = p[1]; lz[i] = p[2];
        }
        #pragma unroll
        for (int j = 0; j < 8; j++) {
            const float* p = recc + ((size_t)b * RDIM + r0 + tx * 8 + j) * 3;
            float rx = p[0], ry = p[1], rz = p[2];
            #pragma unroll
            for (int i = 0; i < 8; i++) {
                float dx = lx[i] - rx, dy = ly[i] - ry, dz = lz[i] - rz;
                float dd = fmaf(dx, dx, fmaf(dy, dy, dz * dz));
                dist[i][j] = sqrt_approx(dd);
            }
        }
    }

    // dot-product accumulators: acc[i][j] = packed (r=2j, r=2j+1) for l-row i
    unsigned long long acc[8][4];
    #pragma unroll
    for (int i = 0; i < 8; i++)
        #pragma unroll
        for (int j = 0; j < 4; j++)
            acc[i][j] = 0ULL;

    float u_acc = 0.0f;

    // ---- prefetch stage 0 into registers ----
    float4 pa0, pa1, pb0, pb1;
    {
        const float* a = Ag + (size_t)lrow * KTOT + lcol;
        pa0 = *(const float4*)a;
        pa1 = *(const float4*)(a + (size_t)64 * KTOT);
        const float* bb = Bg + (size_t)lrow * KTOT + lcol;
        pb0 = *(const float4*)bb;
        pb1 = *(const float4*)(bb + (size_t)64 * KTOT);
    }

    #pragma unroll 1
    for (int s = 0; s < NSTAGE; s++) {
        const int buf = s & 1;
        unsigned long long* Asb = As2 + buf * (KT * 128);
        float* Bsb = Bs + buf * (KT * 128);

        // store prefetched tile to smem (A duplicated as f32x2 pairs)
        {
            float va0[4] = {pa0.x, pa0.y, pa0.z, pa0.w};
            float va1[4] = {pa1.x, pa1.y, pa1.z, pa1.w};
            float vb0[4] = {pb0.x, pb0.y, pb0.z, pb0.w};
            float vb1[4] = {pb1.x, pb1.y, pb1.z, pb1.w};
            #pragma unroll
            for (int j = 0; j < 4; j++) {
                Asb[(lcol + j) * 128 + lrow]      = dup2(va0[j]);
                Asb[(lcol + j) * 128 + lrow + 64] = dup2(va1[j]);
                Bsb[(lcol + j) * 128 + lrow]      = vb0[j];
                Bsb[(lcol + j) * 128 + lrow + 64] = vb1[j];
            }
        }
        __syncthreads();

        // prefetch next stage (global -> regs), latency hidden under compute
        if (s + 1 < NSTAGE) {
            const float* a = Ag + (size_t)lrow * KTOT + (s + 1) * KT + lcol;
            pa0 = *(const float4*)a;
            pa1 = *(const float4*)(a + (size_t)64 * KTOT);
            const float* bb = Bg + (size_t)lrow * KTOT + (s + 1) * KT + lcol;
            pb0 = *(const float4*)bb;
            pb1 = *(const float4*)(bb + (size_t)64 * KTOT);
        }

        // ---- main compute: KT k-steps, 8x8 per thread via f32x2 ----
        #pragma unroll
        for (int k = 0; k < KT; k++) {
            unsigned long long a2[8];
            {
                const ulonglong2* Ar = (const ulonglong2*)(Asb + k * 128 + ty * 8);
                ulonglong2 t0 = Ar[0];
                ulonglong2 t1 = Ar[1];
                ulonglong2 t2 = Ar[2];
                ulonglong2 t3 = Ar[3];
                a2[0] = t0.x; a2[1] = t0.y; a2[2] = t1.x; a2[3] = t1.y;
                a2[4] = t2.x; a2[5] = t2.y; a2[6] = t3.x; a2[7] = t3.y;
            }
            unsigned long long b2[4];
            {
                const ulonglong2* Br = (const ulonglong2*)(Bsb + k * 128 + tx * 8);
                ulonglong2 u0 = Br[0];
                ulonglong2 u1 = Br[1];
                b2[0] = u0.x; b2[1] = u0.y; b2[2] = u1.x; b2[3] = u1.y;
            }
            #pragma unroll
            for (int i = 0; i < 8; i++)
                #pragma unroll
                for (int j = 0; j < 4; j++)
                    fma2(acc[i][j], a2[i], b2[j]);
        }

        // ---- epilogue fold at each e boundary (every FDIM/KT = 4 stages) ----
        if ((s & 3) == 3) {
            const int e = e0 + (s >> 2);
            const float c2 = -(float)e * MU_STEP * KC_CONST;
            #pragma unroll
            for (int i = 0; i < 8; i++) {
                #pragma unroll
                for (int j = 0; j < 4; j++) {
                    float dot0, dot1;
                    unpack2(acc[i][j], dot0, dot1);
                    float w0 = fmaf(dist[i][2 * j],     KC_CONST, c2);
                    float w1 = fmaf(dist[i][2 * j + 1], KC_CONST, c2);
                    float r0f = ex2_approx(-w0 * w0);
                    float r1f = ex2_approx(-w1 * w1);
                    u_acc = fmaf(r0f, dot0, u_acc);
                    u_acc = fmaf(r1f, dot1, u_acc);
                    acc[i][j] = 0ULL;
                }
            }
        }
    }

    // ---- block reduction + atomic accumulate into U[b] ----
    #pragma unroll
    for (int o = 16; o > 0; o >>= 1)
        u_acc += __shfl_xor_sync(0xffffffffu, u_acc, o);

    __syncthreads();                     // done with tile smem, reuse as scratch
    float* red = (float*)smem_u64;
    if ((tid & 31) == 0) red[tid >> 5] = u_acc;
    __syncthreads();
    if (tid == 0) {
        float ssum = 0.0f;
        #pragma unroll
        for (int w = 0; w < NTHREADS / 32; w++) ssum += red[w];
        atomicAdd(out + b, ssum * 0.01f);   // ENERGY_SCALE
    }
}

extern "C" void kernel_launch(void* const* d_in, const int* in_sizes, int n_in,
                              void* d_out, int out_size) {
    const float* lig_feat  = (const float*)d_in[0];
    const float* rec_feat  = (const float*)d_in[1];
    const float* lig_coord = (const float*)d_in[2];
    const float* rec_coord = (const float*)d_in[3];
    float* out = (float*)d_out;

    ff_init_kernel<<<1, 32>>>(out);

    dim3 grid(RDIM / RT, EDIM / ECH, BATCH);   // (16, 8, 8) = 1024 CTAs
    dim3 block(NTHREADS);
    ff_main_kernel<<<grid, block>>>(lig_feat, rec_feat, lig_coord, rec_coord, out);
}

// round 6
// speedup vs baseline: 1.0799x; 1.0799x over previous
#include <cuda_runtime.h>

// Problem constants
#define LDIM   128
#define RDIM   2048
#define EDIM   32
#define FDIM   64
#define KTOT   2048      // EDIM*FDIM, contiguous k per row
#define BATCH  8

// Tiling
#define KT      16       // k per stage
#define RT      128      // r per CTA
#define ECH     4        // e per CTA
#define NSTAGE  ((ECH*FDIM)/KT)   // 16
#define NTHREADS 256

// rbf(d,e) = exp(-((d-mu_e)/sigma)^2) = 2^( -(KC*(d-mu_e))^2 )
#define KC_CONST   3.2029930899845557f
#define MU_STEP    (12.0f/31.0f)

__device__ __forceinline__ unsigned long long dup2(float x) {
    unsigned long long r;
    unsigned int u = __float_as_uint(x);
    asm("mov.b64 %0, {%1, %1};" : "=l"(r) : "r"(u));
    return r;
}
__device__ __forceinline__ void fma2(unsigned long long &acc,
                                     unsigned long long a,
                                     unsigned long long b) {
    asm("fma.rn.f32x2 %0, %1, %2, %0;" : "+l"(acc) : "l"(a), "l"(b));
}
__device__ __forceinline__ void unpack2(unsigned long long v, float &lo, float &hi) {
    unsigned int a, b;
    asm("mov.b64 {%0, %1}, %2;" : "=r"(a), "=r"(b) : "l"(v));
    lo = __uint_as_float(a);
    hi = __uint_as_float(b);
}
__device__ __forceinline__ float ex2_approx(float x) {
    float r;
    asm("ex2.approx.ftz.f32 %0, %1;" : "=f"(r) : "f"(x));
    return r;
}
__device__ __forceinline__ float sqrt_approx(float x) {
    float r;
    asm("sqrt.approx.f32 %0, %1;" : "=f"(r) : "f"(x));
    return r;
}

__global__ void ff_init_kernel(float* out) {
    if (threadIdx.x < BATCH) out[threadIdx.x] = 0.0f;
}

__global__ void __launch_bounds__(NTHREADS, 1)
ff_main_kernel(const float* __restrict__ ligf,
               const float* __restrict__ recf,
               const float* __restrict__ ligc,
               const float* __restrict__ recc,
               float* __restrict__ out)
{
    // Shared: As duplicated pairs [2][KT][128] u64 = 32 KB, Bs [2][KT][128] f32 = 16 KB
    __shared__ unsigned long long smem_u64[49152 / 8];
    unsigned long long* As2 = smem_u64;                       // 2*KT*128 u64
    float* Bs = (float*)(smem_u64 + 2 * KT * 128);            // 2*KT*128 f32

    const int tid = threadIdx.x;
    const int tx = tid & 15;          // r-tile position (8 r's each, strided pairs)
    const int ty = tid >> 4;          // l-tile position (8 l's each)

    const int rt = blockIdx.x;        // 0..15
    const int ec = blockIdx.y;        // 0..7
    const int b  = blockIdx.z;        // 0..7

    const int r0    = rt * RT;
    const int e0    = ec * ECH;
    const int kbase = e0 * FDIM;

    const float* Ag = ligf + (size_t)b * LDIM * KTOT + kbase;
    const float* Bg = recf + (size_t)b * RDIM * KTOT + (size_t)r0 * KTOT + kbase;

    // staging assignment: lane-uniform k row -> conflict-free smem stores.
    // thread loads rows (srow, srow+64), 4 consecutive k at column scol.
    const int srow = tid & 63;            // 0..63
    const int scol = (tid >> 6) * 4;      // 0,4,8,12

    // ---- distances for this thread's 8x8 pairs ----
    // r ownership (strided pairs): j = 2g+h  ->  r_local = 2*tx + 32*g + h
    float dist[8][8];
    {
        float lx[8], ly[8], lz[8];
        #pragma unroll
        for (int i = 0; i < 8; i++) {
            const float* p = ligc + ((size_t)b * LDIM + ty * 8 + i) * 3;
            lx[i] = p[0]; ly[i] = p[1]; lz[i] = p[2];
        }
        #pragma unroll
        for (int g = 0; g < 4; g++) {
            #pragma unroll
            for (int h = 0; h < 2; h++) {
                const int rl = 2 * tx + 32 * g + h;
                const float* p = recc + ((size_t)b * RDIM + r0 + rl) * 3;
                float rx = p[0], ry = p[1], rz = p[2];
                #pragma unroll
                for (int i = 0; i < 8; i++) {
                    float dx = lx[i] - rx, dy = ly[i] - ry, dz = lz[i] - rz;
                    float dd = fmaf(dx, dx, fmaf(dy, dy, dz * dz));
                    dist[i][2 * g + h] = sqrt_approx(dd);
                }
            }
        }
    }

    // acc[i][g] = packed (r = 2tx+32g, r = 2tx+32g+1) for l-row i
    unsigned long long acc[8][4];
    #pragma unroll
    for (int i = 0; i < 8; i++)
        #pragma unroll
        for (int j = 0; j < 4; j++)
            acc[i][j] = 0ULL;

    float u_acc = 0.0f;

    // ---- prefetch stage 0 into registers ----
    float4 pa0, pa1, pb0, pb1;
    {
        const float* a = Ag + (size_t)srow * KTOT + scol;
        pa0 = *(const float4*)a;
        pa1 = *(const float4*)(a + (size_t)64 * KTOT);
        const float* bb = Bg + (size_t)srow * KTOT + scol;
        pb0 = *(const float4*)bb;
        pb1 = *(const float4*)(bb + (size_t)64 * KTOT);
    }

    #pragma unroll 1
    for (int s = 0; s < NSTAGE; s++) {
        const int buf = s & 1;
        unsigned long long* Asb = As2 + buf * (KT * 128);
        float* Bsb = Bs + buf * (KT * 128);

        // store prefetched tile to smem (A duplicated as f32x2 pairs)
        // within a warp: k row uniform per instruction -> conflict-free
        {
            float va0[4] = {pa0.x, pa0.y, pa0.z, pa0.w};
            float va1[4] = {pa1.x, pa1.y, pa1.z, pa1.w};
            float vb0[4] = {pb0.x, pb0.y, pb0.z, pb0.w};
            float vb1[4] = {pb1.x, pb1.y, pb1.z, pb1.w};
            #pragma unroll
            for (int j = 0; j < 4; j++) {
                Asb[(scol + j) * 128 + srow]      = dup2(va0[j]);
                Asb[(scol + j) * 128 + srow + 64] = dup2(va1[j]);
                Bsb[(scol + j) * 128 + srow]      = vb0[j];
                Bsb[(scol + j) * 128 + srow + 64] = vb1[j];
            }
        }
        __syncthreads();

        // prefetch next stage (global -> regs), latency hidden under compute
        if (s + 1 < NSTAGE) {
            const float* a = Ag + (size_t)srow * KTOT + (s + 1) * KT + scol;
            pa0 = *(const float4*)a;
            pa1 = *(const float4*)(a + (size_t)64 * KTOT);
            const float* bb = Bg + (size_t)srow * KTOT + (s + 1) * KT + scol;
            pb0 = *(const float4*)bb;
            pb1 = *(const float4*)(bb + (size_t)64 * KTOT);
        }

        // ---- main compute: KT k-steps, 8x8 per thread via f32x2 ----
        #pragma unroll
        for (int k = 0; k < KT; k++) {
            // A: broadcast LDS.128 (2 distinct ty per warp -> 1 wavefront each)
            unsigned long long a2[8];
            {
                const ulonglong2* Ar = (const ulonglong2*)(Asb + k * 128 + ty * 8);
                ulonglong2 t0 = Ar[0];
                ulonglong2 t1 = Ar[1];
                ulonglong2 t2 = Ar[2];
                ulonglong2 t3 = Ar[3];
                a2[0] = t0.x; a2[1] = t0.y; a2[2] = t1.x; a2[3] = t1.y;
                a2[4] = t2.x; a2[5] = t2.y; a2[6] = t3.x; a2[7] = t3.y;
            }
            // B: strided-pair LDS.64, banks 2*tx%32 -> conflict-free (1 wf each)
            unsigned long long b2[4];
            {
                const unsigned long long* Bp =
                    (const unsigned long long*)(Bsb + k * 128);
                b2[0] = Bp[tx];
                b2[1] = Bp[tx + 16];
                b2[2] = Bp[tx + 32];
                b2[3] = Bp[tx + 48];
            }
            #pragma unroll
            for (int i = 0; i < 8; i++)
                #pragma unroll
                for (int j = 0; j < 4; j++)
                    fma2(acc[i][j], a2[i], b2[j]);
        }

        // ---- epilogue fold at each e boundary (every FDIM/KT = 4 stages) ----
        if ((s & 3) == 3) {
            const int e = e0 + (s >> 2);
            const float c2 = -(float)e * MU_STEP * KC_CONST;
            #pragma unroll
            for (int i = 0; i < 8; i++) {
                #pragma unroll
                for (int j = 0; j < 4; j++) {
                    float dot0, dot1;
                    unpack2(acc[i][j], dot0, dot1);
                    float w0 = fmaf(dist[i][2 * j],     KC_CONST, c2);
                    float w1 = fmaf(dist[i][2 * j + 1], KC_CONST, c2);
                    float r0f = ex2_approx(-w0 * w0);
                    float r1f = ex2_approx(-w1 * w1);
                    u_acc = fmaf(r0f, dot0, u_acc);
                    u_acc = fmaf(r1f, dot1, u_acc);
                    acc[i][j] = 0ULL;
                }
            }
        }
    }

    // ---- block reduction + atomic accumulate into U[b] ----
    #pragma unroll
    for (int o = 16; o > 0; o >>= 1)
        u_acc += __shfl_xor_sync(0xffffffffu, u_acc, o);

    __syncthreads();                     // done with tile smem, reuse as scratch
    float* red = (float*)smem_u64;
    if ((tid & 31) == 0) red[tid >> 5] = u_acc;
    __syncthreads();
    if (tid == 0) {
        float ssum = 0.0f;
        #pragma unroll
        for (int w = 0; w < NTHREADS / 32; w++) ssum += red[w];
        atomicAdd(out + b, ssum * 0.01f);   // ENERGY_SCALE
    }
}

extern "C" void kernel_launch(void* const* d_in, const int* in_sizes, int n_in,
                              void* d_out, int out_size) {
    const float* lig_feat  = (const float*)d_in[0];
    const float* rec_feat  = (const float*)d_in[1];
    const float* lig_coord = (const float*)d_in[2];
    const float* rec_coord = (const float*)d_in[3];
    float* out = (float*)d_out;

    ff_init_kernel<<<1, 32>>>(out);

    dim3 grid(RDIM / RT, EDIM / ECH, BATCH);   // (16, 8, 8) = 1024 CTAs
    dim3 block(NTHREADS);
    ff_main_kernel<<<grid, block>>>(lig_feat, rec_feat, lig_coord, rec_coord, out);
}

// round 7
// speedup vs baseline: 1.4062x; 1.3022x over previous
#include <cuda_runtime.h>

// Problem constants
#define LDIM   128
#define RDIM   2048
#define EDIM   32
#define FDIM   64
#define KTOT   2048      // EDIM*FDIM, contiguous k per row
#define BATCH  8

// Tiling
#define KT       16       // k per stage
#define RT       128      // r per CTA
#define ECH      4        // e per CTA
#define NSTAGE   ((ECH*FDIM)/KT)   // 16
#define NTHREADS 512
#define LDSROW   132      // padded row: bank = (4k + srow) % 32 -> 2-way max

// rbf(d,e) = exp(-((d-mu_e)/sigma)^2) = 2^( -(KC*(d-mu_e))^2 )
#define KC_CONST   3.2029930899845557f
#define MU_STEP    (12.0f/31.0f)

__device__ __forceinline__ unsigned long long dup2(float x) {
    unsigned long long r;
    unsigned int u = __float_as_uint(x);
    asm("mov.b64 %0, {%1, %1};" : "=l"(r) : "r"(u));
    return r;
}
__device__ __forceinline__ void fma2(unsigned long long &acc,
                                     unsigned long long a,
                                     unsigned long long b) {
    asm("fma.rn.f32x2 %0, %1, %2, %0;" : "+l"(acc) : "l"(a), "l"(b));
}
__device__ __forceinline__ void unpack2(unsigned long long v, float &lo, float &hi) {
    unsigned int a, b;
    asm("mov.b64 {%0, %1}, %2;" : "=r"(a), "=r"(b) : "l"(v));
    lo = __uint_as_float(a);
    hi = __uint_as_float(b);
}
__device__ __forceinline__ float ex2_approx(float x) {
    float r;
    asm("ex2.approx.ftz.f32 %0, %1;" : "=f"(r) : "f"(x));
    return r;
}
__device__ __forceinline__ float sqrt_approx(float x) {
    float r;
    asm("sqrt.approx.f32 %0, %1;" : "=f"(r) : "f"(x));
    return r;
}

__global__ void ff_init_kernel(float* out) {
    if (threadIdx.x < BATCH) out[threadIdx.x] = 0.0f;
}

__global__ void __launch_bounds__(NTHREADS, 1)
ff_main_kernel(const float* __restrict__ ligf,
               const float* __restrict__ recf,
               const float* __restrict__ ligc,
               const float* __restrict__ recc,
               float* __restrict__ out)
{
    // A tile [2][KT][LDSROW] + B tile [2][KT][LDSROW], fp32, no duplication.
    __shared__ __align__(16) float smem[2 * KT * LDSROW * 2];   // 33792 B
    float* As = smem;
    float* Bs = smem + 2 * KT * LDSROW;

    const int tid = threadIdx.x;
    const int tx  = tid & 31;          // owns r = 4*tx .. 4*tx+3
    const int w   = tid >> 5;          // warp id; owns l = w*8 .. w*8+7

    const int rt = blockIdx.x;         // 0..15
    const int ec = blockIdx.y;         // 0..7
    const int b  = blockIdx.z;         // 0..7

    const int r0    = rt * RT;
    const int e0    = ec * ECH;
    const int kbase = e0 * FDIM;

    const float* Ag = ligf + (size_t)b * LDIM * KTOT + kbase;
    const float* Bg = recf + (size_t)b * RDIM * KTOT + (size_t)r0 * KTOT + kbase;

    // staging: each thread loads one float4 (4 consecutive k) for one row.
    // 8 rows per warp -> ~8 lines per LDG.128 (coalesced-ish).
    const int srow = tid >> 2;          // 0..127
    const int scol = (tid & 3) * 4;     // 0,4,8,12

    // ---- distances for this thread's 8x4 pairs ----
    float dist[8][4];
    {
        float lx[8], ly[8], lz[8];
        #pragma unroll
        for (int i = 0; i < 8; i++) {
            const float* p = ligc + ((size_t)b * LDIM + w * 8 + i) * 3;
            lx[i] = p[0]; ly[i] = p[1]; lz[i] = p[2];
        }
        #pragma unroll
        for (int j = 0; j < 4; j++) {
            const float* p = recc + ((size_t)b * RDIM + r0 + 4 * tx + j) * 3;
            float rx = p[0], ry = p[1], rz = p[2];
            #pragma unroll
            for (int i = 0; i < 8; i++) {
                float dx = lx[i] - rx, dy = ly[i] - ry, dz = lz[i] - rz;
                float dd = fmaf(dx, dx, fmaf(dy, dy, dz * dz));
                dist[i][j] = sqrt_approx(dd);
            }
        }
    }

    // acc[p][j] = packed {l = w*8+2p, l = w*8+2p+1} x r = 4tx+j
    unsigned long long acc[4][4];
    #pragma unroll
    for (int p = 0; p < 4; p++)
        #pragma unroll
        for (int j = 0; j < 4; j++)
            acc[p][j] = 0ULL;

    float u_acc = 0.0f;

    // ---- prefetch stage 0 into registers ----
    float4 pa, pb;
    {
        pa = *(const float4*)(Ag + (size_t)srow * KTOT + scol);
        pb = *(const float4*)(Bg + (size_t)srow * KTOT + scol);
    }

    #pragma unroll 1
    for (int s = 0; s < NSTAGE; s++) {
        const int buf = s & 1;
        float* Asb = As + buf * (KT * LDSROW);
        float* Bsb = Bs + buf * (KT * LDSROW);

        // store prefetched tile (padded row -> max 2-way bank conflict)
        {
            float va[4] = {pa.x, pa.y, pa.z, pa.w};
            float vb[4] = {pb.x, pb.y, pb.z, pb.w};
            #pragma unroll
            for (int j = 0; j < 4; j++) {
                Asb[(scol + j) * LDSROW + srow] = va[j];
                Bsb[(scol + j) * LDSROW + srow] = vb[j];
            }
        }
        __syncthreads();

        // prefetch next stage (latency hidden under compute)
        if (s + 1 < NSTAGE) {
            pa = *(const float4*)(Ag + (size_t)srow * KTOT + (s + 1) * KT + scol);
            pb = *(const float4*)(Bg + (size_t)srow * KTOT + (s + 1) * KT + scol);
        }

        // ---- main compute: KT k-steps, 8Lx4R per thread via f32x2 ----
        #pragma unroll
        for (int k = 0; k < KT; k++) {
            // A: l-pairs, fully broadcast within warp (2x LDS.128, 1 wf each)
            unsigned long long a2[4];
            {
                const ulonglong2* Ar =
                    (const ulonglong2*)(Asb + k * LDSROW + w * 8);
                ulonglong2 t0 = Ar[0];
                ulonglong2 t1 = Ar[1];
                a2[0] = t0.x; a2[1] = t0.y; a2[2] = t1.x; a2[3] = t1.y;
            }
            // B: 4 consecutive r per lane, LDS.128 conflict-free
            float4 bf = *(const float4*)(Bsb + k * LDSROW + 4 * tx);
            unsigned long long b2[4];
            b2[0] = dup2(bf.x);
            b2[1] = dup2(bf.y);
            b2[2] = dup2(bf.z);
            b2[3] = dup2(bf.w);

            #pragma unroll
            for (int p = 0; p < 4; p++)
                #pragma unroll
                for (int j = 0; j < 4; j++)
                    fma2(acc[p][j], a2[p], b2[j]);
        }

        // ---- epilogue fold at each e boundary (every FDIM/KT = 4 stages) ----
        if ((s & 3) == 3) {
            const int e = e0 + (s >> 2);
            const float c2 = -(float)e * MU_STEP * KC_CONST;
            #pragma unroll
            for (int p = 0; p < 4; p++) {
                #pragma unroll
                for (int j = 0; j < 4; j++) {
                    float dot0, dot1;
                    unpack2(acc[p][j], dot0, dot1);
                    float w0 = fmaf(dist[2 * p][j],     KC_CONST, c2);
                    float w1 = fmaf(dist[2 * p + 1][j], KC_CONST, c2);
                    float r0f = ex2_approx(-w0 * w0);
                    float r1f = ex2_approx(-w1 * w1);
                    u_acc = fmaf(r0f, dot0, u_acc);
                    u_acc = fmaf(r1f, dot1, u_acc);
                    acc[p][j] = 0ULL;
                }
            }
        }
    }

    // ---- block reduction + atomic accumulate into U[b] ----
    #pragma unroll
    for (int o = 16; o > 0; o >>= 1)
        u_acc += __shfl_xor_sync(0xffffffffu, u_acc, o);

    __syncthreads();                     // done with tile smem, reuse as scratch
    float* red = smem;
    if ((tid & 31) == 0) red[w] = u_acc;
    __syncthreads();
    if (tid == 0) {
        float ssum = 0.0f;
        #pragma unroll
        for (int ww = 0; ww < NTHREADS / 32; ww++) ssum += red[ww];
        atomicAdd(out + b, ssum * 0.01f);   // ENERGY_SCALE
    }
}

extern "C" void kernel_launch(void* const* d_in, const int* in_sizes, int n_in,
                              void* d_out, int out_size) {
    const float* lig_feat  = (const float*)d_in[0];
    const float* rec_feat  = (const float*)d_in[1];
    const float* lig_coord = (const float*)d_in[2];
    const float* rec_coord = (const float*)d_in[3];
    float* out = (float*)d_out;

    ff_init_kernel<<<1, 32>>>(out);

    dim3 grid(RDIM / RT, EDIM / ECH, BATCH);   // (16, 8, 8) = 1024 CTAs
    dim3 block(NTHREADS);
    ff_main_kernel<<<grid, block>>>(lig_feat, rec_feat, lig_coord, rec_coord, out);
}